// round 1
// baseline (speedup 1.0000x reference)
#include <cuda_runtime.h>

// GNN_70145405878616
// out[b,o] = tanh(tanh( bc[o] + sum_c Wc[o,c,0]*h[b,c] + Wc[o,c,1]*pooled[b,c] ))
//   h[b,c]      = tanh( bs[c] + sum_j Ws[c,j]*x[b,j] )
//   pooled[b,c] = mean_k neighbors[b,c,k]
//
// B = 1e6 nodes, C = 3, K = 64.  Dominant cost: streaming neighbors (768 MB).
// Strategy: 16 lanes per node; each lane loads one float4 per channel
// (fully coalesced 256B per channel per node), register-reduce, then a
// 4-step shfl_xor tree within the 16-lane group. Lane 0 does the tiny MLP.

__global__ void gnn_kernel(const float* __restrict__ x,
                           const float* __restrict__ nb,
                           const float* __restrict__ Ws,
                           const float* __restrict__ bs,
                           const float* __restrict__ Wc,
                           const float* __restrict__ bc,
                           float* __restrict__ out,
                           int B) {
    const int gtid = blockIdx.x * blockDim.x + threadIdx.x;
    const int node = gtid >> 4;        // 16 lanes per node
    const int lane = gtid & 15;
    if (node >= B) return;

    // 192 floats per node, 16-byte aligned (192*4 = 768B stride)
    const float4* base = reinterpret_cast<const float4*>(nb + (size_t)node * 192);

    // Per-channel partial sums: channel c occupies float4s [c*16, c*16+16)
    float4 v0 = base[lane];
    float4 v1 = base[16 + lane];
    float4 v2 = base[32 + lane];
    float s0 = (v0.x + v0.y) + (v0.z + v0.w);
    float s1 = (v1.x + v1.y) + (v1.z + v1.w);
    float s2 = (v2.x + v2.y) + (v2.z + v2.w);

    // Reduce across the 16-lane group. xor offsets < 16 never cross groups.
    // Mask covers this group's half-warp only (tail-safe if B*16 % 32 != 0).
    const unsigned mask = 0xFFFFu << (threadIdx.x & 16);
    #pragma unroll
    for (int off = 8; off > 0; off >>= 1) {
        s0 += __shfl_xor_sync(mask, s0, off);
        s1 += __shfl_xor_sync(mask, s1, off);
        s2 += __shfl_xor_sync(mask, s2, off);
    }

    if (lane == 0) {
        const float inv = 1.0f / 64.0f;
        float p[3] = { s0 * inv, s1 * inv, s2 * inv };

        const float* xp = x + (size_t)node * 3;
        float x0 = xp[0], x1 = xp[1], x2 = xp[2];

        float h[3];
        #pragma unroll
        for (int o = 0; o < 3; ++o) {
            h[o] = tanhf(fmaf(Ws[o * 3 + 0], x0,
                         fmaf(Ws[o * 3 + 1], x1,
                         fmaf(Ws[o * 3 + 2], x2, bs[o]))));
        }

        float* op = out + (size_t)node * 3;
        #pragma unroll
        for (int o = 0; o < 3; ++o) {
            float z = bc[o];
            #pragma unroll
            for (int c = 0; c < 3; ++c) {
                z = fmaf(Wc[o * 6 + c * 2 + 0], h[c], z);
                z = fmaf(Wc[o * 6 + c * 2 + 1], p[c], z);
            }
            op[o] = tanhf(tanhf(z));
        }
    }
}

extern "C" void kernel_launch(void* const* d_in, const int* in_sizes, int n_in,
                              void* d_out, int out_size) {
    const float* x  = (const float*)d_in[0];   // [B,3,1]
    const float* nb = (const float*)d_in[1];   // [B,3,64]
    const float* Ws = (const float*)d_in[2];   // [3,3]
    const float* bs = (const float*)d_in[3];   // [3]
    const float* Wc = (const float*)d_in[4];   // [3,3,2]
    const float* bc = (const float*)d_in[5];   // [3]
    float* out = (float*)d_out;                // [B,3,1]

    const int B = in_sizes[0] / 3;
    const int threads = 256;                   // 16 nodes per block
    const long long total = (long long)B * 16;
    const int blocks = (int)((total + threads - 1) / threads);

    gnn_kernel<<<blocks, threads>>>(x, nb, Ws, bs, Wc, bc, out, B);
}

// round 2
// speedup vs baseline: 1.4541x; 1.4541x over previous
#include <cuda_runtime.h>

// GNN_70145405878616 — one thread per node.
// out[b,o] = tanh(tanh( bc[o] + sum_c Wc[o,c,0]*h[b,c] + Wc[o,c,1]*p[b,c] ))
//   h[b,c] = tanh( bs[c] + sum_j Ws[c,j]*x[b,j] ),  p[b,c] = mean_k nb[b,c,k]
//
// Dominant cost: streaming neighbors (768 MB). Each thread loads its node's
// 192 floats as 12 float4s (independent -> deep MLP), reduces in registers.
// No shuffles, no shared memory, no predicated epilogue waste.

__device__ __forceinline__ float fast_tanh(float x) {
    // tanh(x) = 1 - 2/(exp(2x)+1); exact at +/-inf saturation.
    float e = __expf(2.0f * x);                 // FMUL + MUFU.EX2
    return 1.0f - __fdividef(2.0f, e + 1.0f);   // MUFU.RCP + FMUL + FADD
}

__global__ __launch_bounds__(256) void gnn_kernel(
        const float* __restrict__ x,
        const float* __restrict__ nb,
        const float* __restrict__ Ws,
        const float* __restrict__ bs,
        const float* __restrict__ Wc,
        const float* __restrict__ bc,
        float* __restrict__ out,
        int B) {
    const int node = blockIdx.x * blockDim.x + threadIdx.x;
    if (node >= B) return;

    const float4* __restrict__ base =
        reinterpret_cast<const float4*>(nb + (size_t)node * 192);

    // Per-channel accumulation; 3 channels x 16 float4 each.
    // Two accumulators per channel to shorten the FADD chain while keeping
    // register count low enough for high occupancy.
    float4 a0 = base[0],  b0 = base[1];
    float4 a1 = base[16], b1 = base[17];
    float4 a2 = base[32], b2 = base[33];
    #pragma unroll
    for (int i = 2; i < 16; i += 2) {
        float4 v;
        v = base[i];          a0.x += v.x; a0.y += v.y; a0.z += v.z; a0.w += v.w;
        v = base[i + 1];      b0.x += v.x; b0.y += v.y; b0.z += v.z; b0.w += v.w;
        v = base[16 + i];     a1.x += v.x; a1.y += v.y; a1.z += v.z; a1.w += v.w;
        v = base[17 + i];     b1.x += v.x; b1.y += v.y; b1.z += v.z; b1.w += v.w;
        v = base[32 + i];     a2.x += v.x; a2.y += v.y; a2.z += v.z; a2.w += v.w;
        v = base[33 + i];     b2.x += v.x; b2.y += v.y; b2.z += v.z; b2.w += v.w;
    }
    const float inv = 1.0f / 64.0f;
    float p0 = ((a0.x + b0.x) + (a0.y + b0.y) + (a0.z + b0.z) + (a0.w + b0.w)) * inv;
    float p1 = ((a1.x + b1.x) + (a1.y + b1.y) + (a1.z + b1.z) + (a1.w + b1.w)) * inv;
    float p2 = ((a2.x + b2.x) + (a2.y + b2.y) + (a2.z + b2.z) + (a2.w + b2.w)) * inv;

    // Self embedding: h = tanh(Ws @ x + bs)
    const float* __restrict__ xp = x + (size_t)node * 3;
    const float x0 = xp[0], x1 = xp[1], x2 = xp[2];

    float h[3], p[3] = {p0, p1, p2};
    #pragma unroll
    for (int o = 0; o < 3; ++o) {
        h[o] = fast_tanh(fmaf(Ws[o * 3 + 0], x0,
                         fmaf(Ws[o * 3 + 1], x1,
                         fmaf(Ws[o * 3 + 2], x2, bs[o]))));
    }

    // Combine conv (k=2) + double tanh
    float* __restrict__ op = out + (size_t)node * 3;
    #pragma unroll
    for (int o = 0; o < 3; ++o) {
        float z = bc[o];
        #pragma unroll
        for (int c = 0; c < 3; ++c) {
            z = fmaf(Wc[o * 6 + c * 2 + 0], h[c], z);
            z = fmaf(Wc[o * 6 + c * 2 + 1], p[c], z);
        }
        op[o] = fast_tanh(fast_tanh(z));
    }
}

extern "C" void kernel_launch(void* const* d_in, const int* in_sizes, int n_in,
                              void* d_out, int out_size) {
    const float* x  = (const float*)d_in[0];   // [B,3,1]
    const float* nb = (const float*)d_in[1];   // [B,3,64]
    const float* Ws = (const float*)d_in[2];   // [3,3]
    const float* bs = (const float*)d_in[3];   // [3]
    const float* Wc = (const float*)d_in[4];   // [3,3,2]
    const float* bc = (const float*)d_in[5];   // [3]
    float* out = (float*)d_out;                // [B,3,1]

    const int B = in_sizes[0] / 3;
    const int threads = 256;
    const int blocks = (B + threads - 1) / threads;

    gnn_kernel<<<blocks, threads>>>(x, nb, Ws, bs, Wc, bc, out, B);
}

// round 4
// speedup vs baseline: 2.0926x; 1.4391x over previous
#include <cuda_runtime.h>

// GNN_70145405878616 — 8 lanes per node, fully coalesced 128B-line loads.
// out[b,o] = tanh(tanh( bc[o] + sum_c Wc[o,c,0]*h[b,c] + Wc[o,c,1]*p[b,c] ))
//   h[b,c] = tanh( bs[c] + sum_j Ws[c,j]*x[b,j] ),  p[b,c] = mean_k nb[b,c,k]
//
// Per node: 192 floats (768 B). 8-lane group: lane l loads float4 c*16+l and
// c*16+8+l per channel -> each group LDG covers one aligned 128B line exactly
// once (768 and 256 are multiples of 128). 6M total L1 wavefronts vs 48M in
// the strided one-thread-per-node version. tanh via MUFU.TANH (1 instr).

__device__ __forceinline__ float htanh(float x) {
    float y;
    asm("tanh.approx.f32 %0, %1;" : "=f"(y) : "f"(x));
    return y;
}

__global__ __launch_bounds__(256) void gnn_kernel(
        const float* __restrict__ x,
        const float* __restrict__ nb,
        const float* __restrict__ Ws,
        const float* __restrict__ bs,
        const float* __restrict__ Wc,
        const float* __restrict__ bc,
        float* __restrict__ out,
        int B) {
    const int gtid = blockIdx.x * blockDim.x + threadIdx.x;
    const int node = gtid >> 3;        // 8 lanes per node
    const int lane = gtid & 7;
    if (node >= B) return;

    const float4* __restrict__ base =
        reinterpret_cast<const float4*>(nb) + (size_t)node * 48;

    // Channel c occupies float4s [c*16, c*16+16). Lane l takes l and l+8.
    float4 a0 = base[lane],      b0 = base[lane + 8];
    float4 a1 = base[lane + 16], b1 = base[lane + 24];
    float4 a2 = base[lane + 32], b2 = base[lane + 40];

    float s0 = ((a0.x + b0.x) + (a0.y + b0.y)) + ((a0.z + b0.z) + (a0.w + b0.w));
    float s1 = ((a1.x + b1.x) + (a1.y + b1.y)) + ((a1.z + b1.z) + (a1.w + b1.w));
    float s2 = ((a2.x + b2.x) + (a2.y + b2.y)) + ((a2.z + b2.z) + (a2.w + b2.w));

    // Reduce across the 8-lane group (xor offsets 4,2,1 stay in-group).
    const unsigned gm = 0xFFu << (threadIdx.x & 24);
    #pragma unroll
    for (int off = 4; off > 0; off >>= 1) {
        s0 += __shfl_xor_sync(gm, s0, off);
        s1 += __shfl_xor_sync(gm, s1, off);
        s2 += __shfl_xor_sync(gm, s2, off);
    }

    if (lane == 0) {
        const float inv = 1.0f / 64.0f;
        float p[3] = { s0 * inv, s1 * inv, s2 * inv };

        const float* __restrict__ xp = x + (size_t)node * 3;
        const float x0 = xp[0], x1 = xp[1], x2 = xp[2];

        float h[3];
        #pragma unroll
        for (int o = 0; o < 3; ++o) {
            h[o] = htanh(fmaf(Ws[o * 3 + 0], x0,
                         fmaf(Ws[o * 3 + 1], x1,
                         fmaf(Ws[o * 3 + 2], x2, bs[o]))));
        }

        float* __restrict__ op = out + (size_t)node * 3;
        #pragma unroll
        for (int o = 0; o < 3; ++o) {
            float z = bc[o];
            #pragma unroll
            for (int c = 0; c < 3; ++c) {
                z = fmaf(Wc[o * 6 + c * 2 + 0], h[c], z);
                z = fmaf(Wc[o * 6 + c * 2 + 1], p[c], z);
            }
            op[o] = htanh(htanh(z));
        }
    }
}

extern "C" void kernel_launch(void* const* d_in, const int* in_sizes, int n_in,
                              void* d_out, int out_size) {
    const float* x  = (const float*)d_in[0];   // [B,3,1]
    const float* nb = (const float*)d_in[1];   // [B,3,64]
    const float* Ws = (const float*)d_in[2];   // [3,3]
    const float* bs = (const float*)d_in[3];   // [3]
    const float* Wc = (const float*)d_in[4];   // [3,3,2]
    const float* bc = (const float*)d_in[5];   // [3]
    float* out = (float*)d_out;                // [B,3,1]

    const int B = in_sizes[0] / 3;
    const int threads = 256;                   // 32 nodes per block
    const long long total = (long long)B * 8;
    const int blocks = (int)((total + threads - 1) / threads);

    gnn_kernel<<<blocks, threads>>>(x, nb, Ws, bs, Wc, bc, out, B);
}